// round 11
// baseline (speedup 1.0000x reference)
#include <cuda_runtime.h>
#include <cuda_fp16.h>
#include <cstddef>

#define NB    512
#define NR    1152
#define NC    10
#define NO    16
#define CO    160          // NC * NO
#define NB2   256          // b-pairs

// flat-permuted inner layout: f = (o>>2)*40 + c*4 + (o&3)

typedef unsigned long long ull;

// ---------------- scratch ----------------------------------------------------------
__device__ __half2 g_uhat2[(size_t)NB2 * NR * CO];  // 189 MB fp16, (even,odd) packed, f-order
__device__ float2  g_S0[NB2 * CO];                  // raw sum_r u_hat (f-order)
__device__ float2  g_S1[NB2 * CO];                  // s from iter 1   (f-order)
__device__ float2  g_S2[NB2 * CO];                  // s from iter 2   (f-order)
__device__ int     g_cnt[NB2];                      // pass-2 completion counters

// ---------------- packed f32x2 helpers ---------------------------------------------
__device__ __forceinline__ ull pk2(float x, float y) {
    ull r; asm("mov.b64 %0, {%1,%2};" : "=l"(r) : "f"(x), "f"(y)); return r;
}
__device__ __forceinline__ void fma2(ull& d, ull a, ull b) {
    asm("fma.rn.f32x2 %0, %1, %2, %0;" : "+l"(d) : "l"(a), "l"(b));
}
__device__ __forceinline__ float2 upk2(ull v) {
    float2 f; asm("mov.b64 {%0,%1}, %2;" : "=f"(f.x), "=f"(f.y) : "l"(v)); return f;
}
__device__ __forceinline__ void redg_v2(float2* p, float x, float y) {
    asm volatile("red.global.add.v2.f32 [%0], {%1, %2};" :: "l"(p), "f"(x), "f"(y) : "memory");
}

// squash over a 16-lane group; all 32 lanes of the warp must call.
__device__ __forceinline__ float squash_val(float s) {
    float sq = s * s;
    sq += __shfl_xor_sync(0xffffffffu, sq, 1);
    sq += __shfl_xor_sync(0xffffffffu, sq, 2);
    sq += __shfl_xor_sync(0xffffffffu, sq, 4);
    sq += __shfl_xor_sync(0xffffffffu, sq, 8);
    return (sqrtf(sq) / (1.0f + sq)) * s;
}

// ---------------- K1: u_hat (fp16 pair-packed, f-order) + raw s0 into S0 -----------
// (unchanged from round 9/10: measured 83us)
#define K1_NBCH 2
#define K1_BCH  (NB / K1_NBCH)    // 256 b
#define K1_NP   (K1_BCH / 2)      // 128 pairs per block

__global__ __launch_bounds__(256, 2) void k1_uhat(const float* __restrict__ u,
                                                  const float* __restrict__ W) {
    __shared__ __align__(16) float2 part[2][8][CO];

    const int w = threadIdx.x >> 5;
    const int l = threadIdx.x & 31;
    const int r = blockIdx.x * 8 + w;
    const int b0 = blockIdx.y * K1_BCH;
    const int pairbase = b0 >> 1;

    ull  Wp01[8], Wp23[8];
    float Wf4[8];
    {
        float Ws[5][8];
#pragma unroll
        for (int k = 0; k < 5; k++) {
            int f = l + 32 * k;
            int c = (f % 40) >> 2;
            int o = (f / 40) * 4 + (f & 3);
            const float* Wq = W + ((size_t)r * NC + c) * 128 + o;
#pragma unroll
            for (int i = 0; i < 8; i++) Ws[k][i] = __ldg(Wq + i * 16);
        }
#pragma unroll
        for (int i = 0; i < 8; i++) {
            Wp01[i] = pk2(Ws[0][i], Ws[1][i]);
            Wp23[i] = pk2(Ws[2][i], Ws[3][i]);
            Wf4[i]  = Ws[4][i];
        }
    }

    const float4* u4 = reinterpret_cast<const float4*>(u);

    auto loadU = [&](float4* P, int bp) {
        const int b = b0 + 2 * bp;
        P[0] = __ldg(&u4[((size_t)b * NR + r) * 2]);
        P[1] = __ldg(&u4[((size_t)b * NR + r) * 2 + 1]);
        P[2] = __ldg(&u4[((size_t)(b + 1) * NR + r) * 2]);
        P[3] = __ldg(&u4[((size_t)(b + 1) * NR + r) * 2 + 1]);
    };

    auto computeOne = [&](const float4* P, int bp, int buf) {
        float ue[8] = {P[0].x, P[0].y, P[0].z, P[0].w, P[1].x, P[1].y, P[1].z, P[1].w};
        float uo[8] = {P[2].x, P[2].y, P[2].z, P[2].w, P[3].x, P[3].y, P[3].z, P[3].w};

        ull a01e = 0ULL, a23e = 0ULL, a01o = 0ULL, a23o = 0ULL;
        float a4e = 0.f, a4o = 0.f;
#pragma unroll
        for (int i = 0; i < 8; i++) {
            ull de = pk2(ue[i], ue[i]);
            ull dq = pk2(uo[i], uo[i]);
            fma2(a01e, de, Wp01[i]);
            fma2(a23e, de, Wp23[i]);
            fma2(a01o, dq, Wp01[i]);
            fma2(a23o, dq, Wp23[i]);
            a4e = fmaf(ue[i], Wf4[i], a4e);
            a4o = fmaf(uo[i], Wf4[i], a4o);
        }
        float2 f01e = upk2(a01e), f23e = upk2(a23e);
        float2 f01o = upk2(a01o), f23o = upk2(a23o);

        __half2* outp = g_uhat2 + ((size_t)(pairbase + bp) * NR + r) * CO;
        outp[l]       = __floats2half2_rn(f01e.x, f01o.x);
        outp[l + 32]  = __floats2half2_rn(f01e.y, f01o.y);
        outp[l + 64]  = __floats2half2_rn(f23e.x, f23o.x);
        outp[l + 96]  = __floats2half2_rn(f23e.y, f23o.y);
        outp[l + 128] = __floats2half2_rn(a4e, a4o);

        part[buf][w][l]       = make_float2(f01e.x, f01o.x);
        part[buf][w][l + 32]  = make_float2(f01e.y, f01o.y);
        part[buf][w][l + 64]  = make_float2(f23e.x, f23o.x);
        part[buf][w][l + 96]  = make_float2(f23e.y, f23o.y);
        part[buf][w][l + 128] = make_float2(a4e, a4o);
    };

    auto reducePair = [&](int bpEven) {
        __syncthreads();
        const int gp = pairbase + bpEven;
        const int t = threadIdx.x;
        {
            int d = (t >= CO) ? 1 : 0;
            int s = t - d * CO;
            float sx = 0.f, sy = 0.f;
#pragma unroll
            for (int ww = 0; ww < 8; ww++) {
                float2 v = part[d][ww][s];
                sx += v.x; sy += v.y;
            }
            redg_v2(&g_S0[(size_t)(gp + d) * CO + s], sx, sy);
        }
        if (t < 64) {
            int s = 96 + t;
            float sx = 0.f, sy = 0.f;
#pragma unroll
            for (int ww = 0; ww < 8; ww++) {
                float2 v = part[1][ww][s];
                sx += v.x; sy += v.y;
            }
            redg_v2(&g_S0[(size_t)(gp + 1) * CO + s], sx, sy);
        }
        __syncthreads();
    };

    float4 A[4], B[4], C[4], D[4];
    loadU(A, 0); loadU(B, 1);

    for (int t = 0; t < K1_NP; t += 4) {
        loadU(C, t + 2); loadU(D, t + 3);
        computeOne(A, t, 0);
        computeOne(B, t + 1, 1);
        reducePair(t);
        if (t + 4 < K1_NP) { loadU(A, t + 4); loadU(B, t + 5); }
        computeOne(C, t + 2, 0);
        computeOne(D, t + 3, 1);
        reducePair(t + 2);
    }
}

// ---------------- pass: routing iteration; V recomputed locally from S-buffers ------
#define RPB     128
#define RCHUNKS (NR / RPB)   // 9

union Q { uint4 v; __half2 h[4]; };

// Gather class-c row from f-ordered S buffer, accumulate squash into V[o].
__device__ __forceinline__ void add_squash_row(const float2* __restrict__ S,
                                               int b2, int c, float scale,
                                               float2* __restrict__ V) {
    const float4* p4 = reinterpret_cast<const float4*>(S + (size_t)b2 * CO);
    float sx[16], sy[16];
    float ssx = 0.f, ssy = 0.f;
#pragma unroll
    for (int oc = 0; oc < 4; oc++)
#pragma unroll
        for (int p = 0; p < 2; p++) {
            float4 t = __ldg(p4 + oc * 20 + c * 2 + p);
            int o = oc * 4 + 2 * p;
            sx[o]     = scale * t.x; sy[o]     = scale * t.y;
            sx[o + 1] = scale * t.z; sy[o + 1] = scale * t.w;
        }
#pragma unroll
    for (int o = 0; o < 16; o++) { ssx = fmaf(sx[o], sx[o], ssx); ssy = fmaf(sy[o], sy[o], ssy); }
    float fx = sqrtf(ssx) / (1.0f + ssx);
    float fy = sqrtf(ssy) / (1.0f + ssy);
#pragma unroll
    for (int o = 0; o < 16; o++) { V[o].x += fx * sx[o]; V[o].y += fy * sy[o]; }
}

__global__ __launch_bounds__(256, 2) void k_pass(float* __restrict__ outp,
                                                 int final_iter) {
    __shared__ float2 part[8][CO];
    __shared__ int lastFlag;

    const int w = threadIdx.x >> 5;
    const int l = threadIdx.x & 31;
    const int b2 = blockIdx.x;
    const int rbase = blockIdx.y * RPB;
    const int g = l >> 4;
    const int c = l & 15;
    const bool act = (c < NC);

    // ---- V prologue: V = squash(0.1*S0) [+ squash(S1) on final iter] --------------
    // V stored as half2(Ve,Vo): one HFMA2 per o computes both batches' dot terms.
    __half2 Vh[16];
    {
        float2 V[16];
#pragma unroll
        for (int o = 0; o < 16; o++) V[o] = make_float2(0.f, 0.f);
        if (act) {
            add_squash_row(g_S0, b2, c, 0.1f, V);
            if (final_iter) add_squash_row(g_S1, b2, c, 1.0f, V);
        }
#pragma unroll
        for (int o = 0; o < 16; o++) Vh[o] = __floats2half2_rn(V[o].x, V[o].y);
    }

    const __half2 hz = __floats2half2_rn(0.f, 0.f);
    __half2 acch[16];
#pragma unroll
    for (int o = 0; o < 16; o++) acch[o] = hz;

    const __half2* base = g_uhat2 + (size_t)b2 * NR * CO + c * 4;
#define PASS_ROW(j) (base + (size_t)(rbase + 2 * (w * 8 + (j)) + g) * CO)

    auto loadq = [&](Q* q, int j) {
        const __half2* rp = PASS_ROW(j);
        q[0].v = __ldg(reinterpret_cast<const uint4*>(rp));
        q[1].v = __ldg(reinterpret_cast<const uint4*>(rp + 40));
        q[2].v = __ldg(reinterpret_cast<const uint4*>(rp + 80));
        q[3].v = __ldg(reinterpret_cast<const uint4*>(rp + 120));
    };

    auto body = [&](Q* q) {
        // fp16 dot: 16 HFMA2 in two chains, no unpack
        __half2 dh0 = hz, dh1 = hz;
        if (act) {
#pragma unroll
            for (int qq = 0; qq < 4; qq++)
#pragma unroll
                for (int m = 0; m < 4; m++) {
                    int o = qq * 4 + m;
                    if (m & 1) dh1 = __hfma2(q[qq].h[m], Vh[o], dh1);
                    else       dh0 = __hfma2(q[qq].h[m], Vh[o], dh0);
                }
        }
        float2 d = __half22float2(__hadd2(dh0, dh1));
        float e0 = act ? __expf(d.x) : 0.0f;        // |logit| small: no max-shift
        float e1 = act ? __expf(d.y) : 0.0f;
        float s0 = e0, s1 = e1;
#pragma unroll
        for (int dl = 1; dl <= 8; dl <<= 1) {
            s0 += __shfl_xor_sync(0xffffffffu, s0, dl);
            s1 += __shfl_xor_sync(0xffffffffu, s1, dl);
        }
        // fp16 accumulate on raw half2: 16 HFMA2, zero unpack/pack
        if (act) {
            __half2 ph = __floats2half2_rn(e0 * __frcp_rn(s0), e1 * __frcp_rn(s1));
#pragma unroll
            for (int qq = 0; qq < 4; qq++)
#pragma unroll
                for (int m = 0; m < 4; m++)
                    acch[qq * 4 + m] = __hfma2(q[qq].h[m], ph, acch[qq * 4 + m]);
        }
    };

    Q qa[4], qb[4];
    if (act) loadq(qa, 0);
#pragma unroll
    for (int j = 0; j < 8; j += 2) {
        if (act) loadq(qb, j + 1);
        body(qa);
        if (act && j + 2 < 8) loadq(qa, j + 2);
        body(qb);
    }

    // flush fp16 -> f32, combine the two 16-lane r-groups, stage into smem (f-order)
#pragma unroll
    for (int o = 0; o < 16; o++) {
        float2 a = __half22float2(acch[o]);
        a.x += __shfl_xor_sync(0xffffffffu, a.x, 16);
        a.y += __shfl_xor_sync(0xffffffffu, a.y, 16);
        if (g == 0 && act) part[w][(o >> 2) * 40 + c * 4 + (o & 3)] = a;
    }
    __syncthreads();

    float2* Sdst = final_iter ? g_S2 : g_S1;
    if (threadIdx.x < CO) {
        float sx = 0.f, sy = 0.f;
#pragma unroll
        for (int ww = 0; ww < 8; ww++) {
            float2 v = part[ww][threadIdx.x];
            sx += v.x; sy += v.y;
        }
        redg_v2(&Sdst[b2 * CO + threadIdx.x], sx, sy);
    }

    if (!final_iter) return;   // pass 1 has no tail

    // ---- pass-2 tail: last of the 9 blocks for this b2 squashes & resets ----------
    __threadfence();
    __syncthreads();
    if (threadIdx.x == 0)
        lastFlag = (atomicAdd(&g_cnt[b2], 1) == RCHUNKS - 1);
    __syncthreads();

    if (lastFlag) {
        __threadfence();
        const int t = threadIdx.x;
        if (t < CO) {                       // 16-lane groups = classes
            int f = ((t & 15) >> 2) * 40 + ((t >> 4) << 2) + (t & 3);
            float2 sv = g_S2[b2 * CO + f];
            float vx = squash_val(sv.x);
            float vy = squash_val(sv.y);
            outp[(2 * b2) * CO + t]     = vx;
            outp[(2 * b2 + 1) * CO + t] = vy;
            g_S0[b2 * CO + f] = make_float2(0.f, 0.f);   // replay invariants
            g_S1[b2 * CO + f] = make_float2(0.f, 0.f);
            g_S2[b2 * CO + f] = make_float2(0.f, 0.f);
        }
        if (threadIdx.x == 0) g_cnt[b2] = 0;
    }
}

// ---------------- launch -------------------------------------------------------------
extern "C" void kernel_launch(void* const* d_in, const int* in_sizes, int n_in,
                              void* d_out, int out_size) {
    const float* u = (const float*)d_in[0];   // [512,1152,8]
    const float* W = (const float*)d_in[1];   // [1,1152,10,8,16]
    float* outp = (float*)d_out;              // [512,10,16]

    k1_uhat<<<dim3(NR / 8, K1_NBCH), 256>>>(u, W);     // u_hat + raw s0 -> S0
    k_pass<<<dim3(NB2, RCHUNKS), 256>>>(outp, 0);      // iter 1 -> S1
    k_pass<<<dim3(NB2, RCHUNKS), 256>>>(outp, 1);      // iter 2 -> S2 -> out, resets
}

// round 13
// speedup vs baseline: 1.1709x; 1.1709x over previous
#include <cuda_runtime.h>
#include <cuda_fp16.h>
#include <cstddef>

#define NB    512
#define NR    1152
#define NC    10
#define NO    16
#define CO    160          // NC * NO
#define NB2   256          // b-pairs

// flat-permuted inner layout: f = (o>>2)*40 + c*4 + (o&3)

typedef unsigned long long ull;

// ---------------- scratch ----------------------------------------------------------
__device__ __half2 g_uhat2[(size_t)NB2 * NR * CO];  // 189 MB fp16, (even,odd) packed, f-order
__device__ float2  g_S0[NB2 * CO];                  // raw sum_r u_hat (f-order)
__device__ float2  g_S1[NB2 * CO];                  // s from iter 1   (f-order)
__device__ float2  g_S2[NB2 * CO];                  // s from iter 2   (f-order)
__device__ int     g_cnt[NB2];                      // pass-2 completion counters

// ---------------- packed f32x2 helpers ---------------------------------------------
__device__ __forceinline__ ull pk2(float x, float y) {
    ull r; asm("mov.b64 %0, {%1,%2};" : "=l"(r) : "f"(x), "f"(y)); return r;
}
__device__ __forceinline__ void fma2(ull& d, ull a, ull b) {
    asm("fma.rn.f32x2 %0, %1, %2, %0;" : "+l"(d) : "l"(a), "l"(b));
}
__device__ __forceinline__ float2 upk2(ull v) {
    float2 f; asm("mov.b64 {%0,%1}, %2;" : "=f"(f.x), "=f"(f.y) : "l"(v)); return f;
}
__device__ __forceinline__ void redg_v2(float2* p, float x, float y) {
    asm volatile("red.global.add.v2.f32 [%0], {%1, %2};" :: "l"(p), "f"(x), "f"(y) : "memory");
}

// squash over a 16-lane group; all 32 lanes of the warp must call.
__device__ __forceinline__ float squash_val(float s) {
    float sq = s * s;
    sq += __shfl_xor_sync(0xffffffffu, sq, 1);
    sq += __shfl_xor_sync(0xffffffffu, sq, 2);
    sq += __shfl_xor_sync(0xffffffffu, sq, 4);
    sq += __shfl_xor_sync(0xffffffffu, sq, 8);
    return (sqrtf(sq) / (1.0f + sq)) * s;
}

// ---------------- K1: u_hat (fp16 pair-packed, f-order) + raw s0 into S0 -----------
// (unchanged: measured ~84us)
#define K1_NBCH 2
#define K1_BCH  (NB / K1_NBCH)    // 256 b
#define K1_NP   (K1_BCH / 2)      // 128 pairs per block

__global__ __launch_bounds__(256, 2) void k1_uhat(const float* __restrict__ u,
                                                  const float* __restrict__ W) {
    __shared__ __align__(16) float2 part[2][8][CO];

    const int w = threadIdx.x >> 5;
    const int l = threadIdx.x & 31;
    const int r = blockIdx.x * 8 + w;
    const int b0 = blockIdx.y * K1_BCH;
    const int pairbase = b0 >> 1;

    ull  Wp01[8], Wp23[8];
    float Wf4[8];
    {
        float Ws[5][8];
#pragma unroll
        for (int k = 0; k < 5; k++) {
            int f = l + 32 * k;
            int c = (f % 40) >> 2;
            int o = (f / 40) * 4 + (f & 3);
            const float* Wq = W + ((size_t)r * NC + c) * 128 + o;
#pragma unroll
            for (int i = 0; i < 8; i++) Ws[k][i] = __ldg(Wq + i * 16);
        }
#pragma unroll
        for (int i = 0; i < 8; i++) {
            Wp01[i] = pk2(Ws[0][i], Ws[1][i]);
            Wp23[i] = pk2(Ws[2][i], Ws[3][i]);
            Wf4[i]  = Ws[4][i];
        }
    }

    const float4* u4 = reinterpret_cast<const float4*>(u);

    auto loadU = [&](float4* P, int bp) {
        const int b = b0 + 2 * bp;
        P[0] = __ldg(&u4[((size_t)b * NR + r) * 2]);
        P[1] = __ldg(&u4[((size_t)b * NR + r) * 2 + 1]);
        P[2] = __ldg(&u4[((size_t)(b + 1) * NR + r) * 2]);
        P[3] = __ldg(&u4[((size_t)(b + 1) * NR + r) * 2 + 1]);
    };

    auto computeOne = [&](const float4* P, int bp, int buf) {
        float ue[8] = {P[0].x, P[0].y, P[0].z, P[0].w, P[1].x, P[1].y, P[1].z, P[1].w};
        float uo[8] = {P[2].x, P[2].y, P[2].z, P[2].w, P[3].x, P[3].y, P[3].z, P[3].w};

        ull a01e = 0ULL, a23e = 0ULL, a01o = 0ULL, a23o = 0ULL;
        float a4e = 0.f, a4o = 0.f;
#pragma unroll
        for (int i = 0; i < 8; i++) {
            ull de = pk2(ue[i], ue[i]);
            ull dq = pk2(uo[i], uo[i]);
            fma2(a01e, de, Wp01[i]);
            fma2(a23e, de, Wp23[i]);
            fma2(a01o, dq, Wp01[i]);
            fma2(a23o, dq, Wp23[i]);
            a4e = fmaf(ue[i], Wf4[i], a4e);
            a4o = fmaf(uo[i], Wf4[i], a4o);
        }
        float2 f01e = upk2(a01e), f23e = upk2(a23e);
        float2 f01o = upk2(a01o), f23o = upk2(a23o);

        __half2* outp = g_uhat2 + ((size_t)(pairbase + bp) * NR + r) * CO;
        outp[l]       = __floats2half2_rn(f01e.x, f01o.x);
        outp[l + 32]  = __floats2half2_rn(f01e.y, f01o.y);
        outp[l + 64]  = __floats2half2_rn(f23e.x, f23o.x);
        outp[l + 96]  = __floats2half2_rn(f23e.y, f23o.y);
        outp[l + 128] = __floats2half2_rn(a4e, a4o);

        part[buf][w][l]       = make_float2(f01e.x, f01o.x);
        part[buf][w][l + 32]  = make_float2(f01e.y, f01o.y);
        part[buf][w][l + 64]  = make_float2(f23e.x, f23o.x);
        part[buf][w][l + 96]  = make_float2(f23e.y, f23o.y);
        part[buf][w][l + 128] = make_float2(a4e, a4o);
    };

    auto reducePair = [&](int bpEven) {
        __syncthreads();
        const int gp = pairbase + bpEven;
        const int t = threadIdx.x;
        {
            int d = (t >= CO) ? 1 : 0;
            int s = t - d * CO;
            float sx = 0.f, sy = 0.f;
#pragma unroll
            for (int ww = 0; ww < 8; ww++) {
                float2 v = part[d][ww][s];
                sx += v.x; sy += v.y;
            }
            redg_v2(&g_S0[(size_t)(gp + d) * CO + s], sx, sy);
        }
        if (t < 64) {
            int s = 96 + t;
            float sx = 0.f, sy = 0.f;
#pragma unroll
            for (int ww = 0; ww < 8; ww++) {
                float2 v = part[1][ww][s];
                sx += v.x; sy += v.y;
            }
            redg_v2(&g_S0[(size_t)(gp + 1) * CO + s], sx, sy);
        }
        __syncthreads();
    };

    float4 A[4], B[4], C[4], D[4];
    loadU(A, 0); loadU(B, 1);

    for (int t = 0; t < K1_NP; t += 4) {
        loadU(C, t + 2); loadU(D, t + 3);
        computeOne(A, t, 0);
        computeOne(B, t + 1, 1);
        reducePair(t);
        if (t + 4 < K1_NP) { loadU(A, t + 4); loadU(B, t + 5); }
        computeOne(C, t + 2, 0);
        computeOne(D, t + 3, 1);
        reducePair(t + 2);
    }
}

// ---------------- pass: routing iteration; V recomputed locally from S-buffers ------
#define RPB     128
#define RCHUNKS (NR / RPB)   // 9

union Q { uint4 v; __half2 h[4]; };

// Gather class-c row from f-ordered S buffer, accumulate squash into V[o].
__device__ __forceinline__ void add_squash_row(const float2* __restrict__ S,
                                               int b2, int c, float scale,
                                               float2* __restrict__ V) {
    const float4* p4 = reinterpret_cast<const float4*>(S + (size_t)b2 * CO);
    float sx[16], sy[16];
    float ssx = 0.f, ssy = 0.f;
#pragma unroll
    for (int oc = 0; oc < 4; oc++)
#pragma unroll
        for (int p = 0; p < 2; p++) {
            float4 t = __ldg(p4 + oc * 20 + c * 2 + p);
            int o = oc * 4 + 2 * p;
            sx[o]     = scale * t.x; sy[o]     = scale * t.y;
            sx[o + 1] = scale * t.z; sy[o + 1] = scale * t.w;
        }
#pragma unroll
    for (int o = 0; o < 16; o++) { ssx = fmaf(sx[o], sx[o], ssx); ssy = fmaf(sy[o], sy[o], ssy); }
    float fx = sqrtf(ssx) / (1.0f + ssx);
    float fy = sqrtf(ssy) / (1.0f + ssy);
#pragma unroll
    for (int o = 0; o < 16; o++) { V[o].x += fx * sx[o]; V[o].y += fy * sy[o]; }
}

__global__ __launch_bounds__(256, 3) void k_pass(float* __restrict__ outp,
                                                 int final_iter) {
    __shared__ float2 part[8][CO];
    __shared__ int lastFlag;

    const int w = threadIdx.x >> 5;
    const int l = threadIdx.x & 31;
    const int b2 = blockIdx.x;
    const int rbase = blockIdx.y * RPB;
    const int g = l >> 4;
    const int c = l & 15;
    const bool act = (c < NC);

    // ---- V prologue: V = squash(0.1*S0) [+ squash(S1) on final iter] --------------
    // V stored half2(Ve,Vo): 16 regs, enabling 3 CTAs/SM.
    __half2 Vh[16];
    {
        float2 V[16];
#pragma unroll
        for (int o = 0; o < 16; o++) V[o] = make_float2(0.f, 0.f);
        if (act) {
            add_squash_row(g_S0, b2, c, 0.1f, V);
            if (final_iter) add_squash_row(g_S1, b2, c, 1.0f, V);
        }
#pragma unroll
        for (int o = 0; o < 16; o++) Vh[o] = __floats2half2_rn(V[o].x, V[o].y);
    }

    const __half2 hz = __floats2half2_rn(0.f, 0.f);
    __half2 acch[16];
#pragma unroll
    for (int o = 0; o < 16; o++) acch[o] = hz;

    const __half2* base = g_uhat2 + (size_t)b2 * NR * CO + c * 4;
#define PASS_ROW(j) (base + (size_t)(rbase + 2 * (w * 8 + (j)) + g) * CO)

    auto loadq = [&](Q* q, int j) {
        const __half2* rp = PASS_ROW(j);
        q[0].v = __ldg(reinterpret_cast<const uint4*>(rp));
        q[1].v = __ldg(reinterpret_cast<const uint4*>(rp + 40));
        q[2].v = __ldg(reinterpret_cast<const uint4*>(rp + 80));
        q[3].v = __ldg(reinterpret_cast<const uint4*>(rp + 120));
    };

    auto body = [&](Q* q) {
        // fp16 dot: 16 HFMA2 in two chains, no unpack
        __half2 dh0 = hz, dh1 = hz;
        if (act) {
#pragma unroll
            for (int qq = 0; qq < 4; qq++)
#pragma unroll
                for (int m = 0; m < 4; m++) {
                    int o = qq * 4 + m;
                    if (m & 1) dh1 = __hfma2(q[qq].h[m], Vh[o], dh1);
                    else       dh0 = __hfma2(q[qq].h[m], Vh[o], dh0);
                }
        }
        float2 d = __half22float2(__hadd2(dh0, dh1));
        float e0 = act ? __expf(d.x) : 0.0f;        // |logit| small: no max-shift
        float e1 = act ? __expf(d.y) : 0.0f;
        float s0 = e0, s1 = e1;
#pragma unroll
        for (int dl = 1; dl <= 8; dl <<= 1) {
            s0 += __shfl_xor_sync(0xffffffffu, s0, dl);
            s1 += __shfl_xor_sync(0xffffffffu, s1, dl);
        }
        // fp16 accumulate on raw half2: 16 HFMA2, zero unpack/pack
        if (act) {
            __half2 ph = __floats2half2_rn(e0 * __frcp_rn(s0), e1 * __frcp_rn(s1));
#pragma unroll
            for (int qq = 0; qq < 4; qq++)
#pragma unroll
                for (int m = 0; m < 4; m++)
                    acch[qq * 4 + m] = __hfma2(q[qq].h[m], ph, acch[qq * 4 + m]);
        }
    };

    Q qa[4], qb[4];
    if (act) loadq(qa, 0);
#pragma unroll
    for (int j = 0; j < 8; j += 2) {
        if (act) loadq(qb, j + 1);
        body(qa);
        if (act && j + 2 < 8) loadq(qa, j + 2);
        body(qb);
    }

    // flush fp16 -> f32, combine the two 16-lane r-groups, stage into smem (f-order)
#pragma unroll
    for (int o = 0; o < 16; o++) {
        float2 a = __half22float2(acch[o]);
        a.x += __shfl_xor_sync(0xffffffffu, a.x, 16);
        a.y += __shfl_xor_sync(0xffffffffu, a.y, 16);
        if (g == 0 && act) part[w][(o >> 2) * 40 + c * 4 + (o & 3)] = a;
    }
    __syncthreads();

    float2* Sdst = final_iter ? g_S2 : g_S1;
    if (threadIdx.x < CO) {
        float sx = 0.f, sy = 0.f;
#pragma unroll
        for (int ww = 0; ww < 8; ww++) {
            float2 v = part[ww][threadIdx.x];
            sx += v.x; sy += v.y;
        }
        redg_v2(&Sdst[b2 * CO + threadIdx.x], sx, sy);
    }

    if (!final_iter) return;   // pass 1 has no tail

    // ---- pass-2 tail: last of the 9 blocks for this b2 squashes & resets ----------
    __threadfence();
    __syncthreads();
    if (threadIdx.x == 0)
        lastFlag = (atomicAdd(&g_cnt[b2], 1) == RCHUNKS - 1);
    __syncthreads();

    if (lastFlag) {
        __threadfence();
        const int t = threadIdx.x;
        if (t < CO) {                       // 16-lane groups = classes
            int f = ((t & 15) >> 2) * 40 + ((t >> 4) << 2) + (t & 3);
            float2 sv = g_S2[b2 * CO + f];
            float vx = squash_val(sv.x);
            float vy = squash_val(sv.y);
            outp[(2 * b2) * CO + t]     = vx;
            outp[(2 * b2 + 1) * CO + t] = vy;
            g_S0[b2 * CO + f] = make_float2(0.f, 0.f);   // replay invariants
            g_S1[b2 * CO + f] = make_float2(0.f, 0.f);
            g_S2[b2 * CO + f] = make_float2(0.f, 0.f);
        }
        if (threadIdx.x == 0) g_cnt[b2] = 0;
    }
}

// ---------------- launch -------------------------------------------------------------
extern "C" void kernel_launch(void* const* d_in, const int* in_sizes, int n_in,
                              void* d_out, int out_size) {
    const float* u = (const float*)d_in[0];   // [512,1152,8]
    const float* W = (const float*)d_in[1];   // [1,1152,10,8,16]
    float* outp = (float*)d_out;              // [512,10,16]

    k1_uhat<<<dim3(NR / 8, K1_NBCH), 256>>>(u, W);     // u_hat + raw s0 -> S0
    k_pass<<<dim3(NB2, RCHUNKS), 256>>>(outp, 0);      // iter 1 -> S1
    k_pass<<<dim3(NB2, RCHUNKS), 256>>>(outp, 1);      // iter 2 -> S2 -> out, resets
}